// round 17
// baseline (speedup 1.0000x reference)
#include <cuda_runtime.h>
#include <cstdint>

#define N_NODES 50000
#define N_EDGES 800000
#define D 128
#define NCLS 64
#define SCAN_B 1024
#define SCAN_NBLK ((N_NODES + SCAN_B - 1) / SCAN_B)   // 49
#define HALF 25024                                    // 391 * 64

// ---------------------------------------------------------------------------
// Device-global scratch
// ---------------------------------------------------------------------------
__device__ __align__(16) float g_y[N_NODES * D];
__device__ __align__(16) float g_h[N_NODES * D];
__device__ __align__(16) float g_z[N_NODES * D];
__device__ int g_row_ptr[N_NODES + 1];
__device__ int g_cursor[N_NODES];
__device__ int g_cnt[N_NODES];
__device__ int g_col[N_EDGES];
__device__ int g_partials[SCAN_NBLK];

// Streams + events created once at static-init (outside capture & checkpoints)
struct OverlapCtx {
    cudaStream_t s1;
    cudaEvent_t evFork, evCSR, evA1, evG2B, evA2, evG3A, evG3B, evFinal;
    OverlapCtx() {
        cudaStreamCreateWithFlags(&s1, cudaStreamNonBlocking);
        cudaEventCreateWithFlags(&evFork,  cudaEventDisableTiming);
        cudaEventCreateWithFlags(&evCSR,   cudaEventDisableTiming);
        cudaEventCreateWithFlags(&evA1,    cudaEventDisableTiming);
        cudaEventCreateWithFlags(&evG2B,   cudaEventDisableTiming);
        cudaEventCreateWithFlags(&evA2,    cudaEventDisableTiming);
        cudaEventCreateWithFlags(&evG3A,   cudaEventDisableTiming);
        cudaEventCreateWithFlags(&evG3B,   cudaEventDisableTiming);
        cudaEventCreateWithFlags(&evFinal, cudaEventDisableTiming);
    }
};
static OverlapCtx g_ctx;

// ---------------------------------------------------------------------------
// CSR kernels — 8 edges/thread (verified R16)
// ---------------------------------------------------------------------------
__global__ void __launch_bounds__(256) hist_kernel(
    const int* __restrict__ dst, int* __restrict__ cnt)
{
    int base = (blockIdx.x * blockDim.x + threadIdx.x) * 8;
    if (base + 7 < N_EDGES) {
        int4 a = *reinterpret_cast<const int4*>(dst + base);
        int4 b = *reinterpret_cast<const int4*>(dst + base + 4);
        atomicAdd(cnt + a.x, 1); atomicAdd(cnt + a.y, 1);
        atomicAdd(cnt + a.z, 1); atomicAdd(cnt + a.w, 1);
        atomicAdd(cnt + b.x, 1); atomicAdd(cnt + b.y, 1);
        atomicAdd(cnt + b.z, 1); atomicAdd(cnt + b.w, 1);
    } else {
        for (int e = base; e < N_EDGES; e++) atomicAdd(cnt + dst[e], 1);
    }
}

__global__ void __launch_bounds__(SCAN_B) scan_block_kernel(
    const int* __restrict__ cnt, int* __restrict__ row_ptr, int* __restrict__ partials)
{
    __shared__ int wsum[32];
    int i = blockIdx.x * SCAN_B + threadIdx.x;
    int lane = threadIdx.x & 31;
    int wid  = threadIdx.x >> 5;

    int v = (i < N_NODES) ? cnt[i] : 0;
    int x = v;
    #pragma unroll
    for (int off = 1; off < 32; off <<= 1) {
        int t = __shfl_up_sync(0xffffffffu, x, off);
        if (lane >= off) x += t;
    }
    if (lane == 31) wsum[wid] = x;
    __syncthreads();
    if (wid == 0) {
        int w = wsum[lane];
        #pragma unroll
        for (int off = 1; off < 32; off <<= 1) {
            int t = __shfl_up_sync(0xffffffffu, w, off);
            if (lane >= off) w += t;
        }
        wsum[lane] = w;
    }
    __syncthreads();

    int excl = x - v + (wid ? wsum[wid - 1] : 0);
    if (i < N_NODES) row_ptr[i] = excl;
    if (threadIdx.x == SCAN_B - 1) partials[blockIdx.x] = excl + v;
}

__global__ void __launch_bounds__(SCAN_B) scan_add_kernel(
    int* __restrict__ row_ptr, int* __restrict__ cursor, const int* __restrict__ partials)
{
    __shared__ int sp[SCAN_NBLK];
    if (threadIdx.x < SCAN_NBLK) sp[threadIdx.x] = partials[threadIdx.x];
    __syncthreads();
    if (threadIdx.x == 0) {
        int run = 0;
        #pragma unroll
        for (int k = 0; k < SCAN_NBLK; k++) { int t = sp[k]; sp[k] = run; run += t; }
    }
    __syncthreads();

    int i = blockIdx.x * SCAN_B + threadIdx.x;
    if (i < N_NODES) {
        int r = row_ptr[i] + sp[blockIdx.x];
        row_ptr[i] = r;
        cursor[i]  = r;
    }
    if (i == 0) row_ptr[N_NODES] = N_EDGES;
}

__global__ void __launch_bounds__(256) fill_kernel(
    const int* __restrict__ src, const int* __restrict__ dst,
    int* __restrict__ cursor, int* __restrict__ col)
{
    int base = (blockIdx.x * blockDim.x + threadIdx.x) * 8;
    if (base + 7 < N_EDGES) {
        int4 da = *reinterpret_cast<const int4*>(dst + base);
        int4 db = *reinterpret_cast<const int4*>(dst + base + 4);
        int4 sa = *reinterpret_cast<const int4*>(src + base);
        int4 sb = *reinterpret_cast<const int4*>(src + base + 4);
        int p0 = atomicAdd(cursor + da.x, 1);
        int p1 = atomicAdd(cursor + da.y, 1);
        int p2 = atomicAdd(cursor + da.z, 1);
        int p3 = atomicAdd(cursor + da.w, 1);
        int p4 = atomicAdd(cursor + db.x, 1);
        int p5 = atomicAdd(cursor + db.y, 1);
        int p6 = atomicAdd(cursor + db.z, 1);
        int p7 = atomicAdd(cursor + db.w, 1);
        col[p0] = sa.x; col[p1] = sa.y; col[p2] = sa.z; col[p3] = sa.w;
        col[p4] = sb.x; col[p5] = sb.y; col[p6] = sb.z; col[p7] = sb.w;
    } else {
        for (int e = base; e < N_EDGES; e++) {
            int pos = atomicAdd(cursor + dst[e], 1);
            col[pos] = src[e];
        }
    }
}

// ---------------------------------------------------------------------------
// f32x2 GEMM — R14/R16 frozen config + row_base/row_limit range params.
// ---------------------------------------------------------------------------
template <int NOUT>
__global__ void __launch_bounds__(128, 4) gemm_kernel(
    const float* __restrict__ A, const float* __restrict__ W,
    float* __restrict__ y, int row_base, int row_limit)
{
    constexpr int BM   = 64;
    constexpr int KC   = 64;
    constexpr int TX   = NOUT / 8;
    constexpr int TY   = 128 / TX;
    constexpr int RPT  = BM / TY;
    constexpr int SXS  = KC + 4;
    constexpr int SWS  = NOUT + 4;
    constexpr int HALFN = NOUT / 2;

    extern __shared__ float smem[];
    float* sX = smem;
    float* sW = smem + BM * SXS;

    const int tid  = threadIdx.x;
    const int row0 = row_base + blockIdx.x * BM;

    const int tx = tid % TX;
    const int ty = tid / TX;
    const int cb0 = tx * 4;
    const int cb1 = HALFN + tx * 4;
    const int rbase = ty * RPT;

    unsigned long long acc[RPT][4];
    #pragma unroll
    for (int r = 0; r < RPT; r++)
        #pragma unroll
        for (int c = 0; c < 4; c++) acc[r][c] = 0ULL;

    #pragma unroll
    for (int kc = 0; kc < D; kc += KC) {
        #pragma unroll
        for (int i = tid; i < BM * (KC / 4); i += 128) {
            int r  = i >> 4;
            int c4 = i & 15;
            int gr = row0 + r;
            float4 v = make_float4(0.f, 0.f, 0.f, 0.f);
            if (gr < row_limit)
                v = *reinterpret_cast<const float4*>(A + (size_t)gr * D + kc + c4 * 4);
            reinterpret_cast<float4*>(sX + r * SXS)[c4] = v;
        }
        #pragma unroll
        for (int i = tid; i < NOUT * (KC / 4); i += 128) {
            int n  = i >> 4;
            int k4 = i & 15;
            float4 v = *reinterpret_cast<const float4*>(W + (size_t)n * D + kc + k4 * 4);
            sW[(k4 * 4 + 0) * SWS + n] = v.x;
            sW[(k4 * 4 + 1) * SWS + n] = v.y;
            sW[(k4 * 4 + 2) * SWS + n] = v.z;
            sW[(k4 * 4 + 3) * SWS + n] = v.w;
        }
        __syncthreads();

        #pragma unroll 2
        for (int k4 = 0; k4 < KC; k4 += 4) {
            float4 av[RPT];
            #pragma unroll
            for (int r = 0; r < RPT; r++)
                av[r] = *reinterpret_cast<const float4*>(sX + (rbase + r) * SXS + k4);

            #pragma unroll
            for (int kk = 0; kk < 4; kk++) {
                const float* swk = sW + (k4 + kk) * SWS;
                ulonglong2 b0 = *reinterpret_cast<const ulonglong2*>(swk + cb0);
                ulonglong2 b1 = *reinterpret_cast<const ulonglong2*>(swk + cb1);
                #pragma unroll
                for (int r = 0; r < RPT; r++) {
                    float a = (kk == 0) ? av[r].x : (kk == 1) ? av[r].y
                            : (kk == 2) ? av[r].z : av[r].w;
                    unsigned long long a2;
                    asm("mov.b64 %0, {%1, %1};" : "=l"(a2) : "f"(a));
                    asm("fma.rn.f32x2 %0, %1, %2, %0;" : "+l"(acc[r][0]) : "l"(a2), "l"(b0.x));
                    asm("fma.rn.f32x2 %0, %1, %2, %0;" : "+l"(acc[r][1]) : "l"(a2), "l"(b0.y));
                    asm("fma.rn.f32x2 %0, %1, %2, %0;" : "+l"(acc[r][2]) : "l"(a2), "l"(b1.x));
                    asm("fma.rn.f32x2 %0, %1, %2, %0;" : "+l"(acc[r][3]) : "l"(a2), "l"(b1.y));
                }
            }
        }
        __syncthreads();
    }

    #pragma unroll
    for (int r = 0; r < RPT; r++) {
        int row = row0 + rbase + r;
        if (row >= row_limit) continue;
        float o[8];
        #pragma unroll
        for (int c = 0; c < 4; c++)
            asm("mov.b64 {%0, %1}, %2;" : "=f"(o[2*c]), "=f"(o[2*c+1]) : "l"(acc[r][c]));
        *reinterpret_cast<float4*>(y + (size_t)row * NOUT + cb0) =
            make_float4(o[0], o[1], o[2], o[3]);
        *reinterpret_cast<float4*>(y + (size_t)row * NOUT + cb1) =
            make_float4(o[4], o[5], o[6], o[7]);
    }
}

// ---------------------------------------------------------------------------
// CSR aggregation + bias + relu, node sub-range (frozen unroll-4 body)
// ---------------------------------------------------------------------------
__global__ void __launch_bounds__(256) aggregate128_kernel(
    const float* __restrict__ y, const int* __restrict__ row_ptr,
    const int* __restrict__ col, const float* __restrict__ bias,
    float* __restrict__ out, int node_base, int node_limit)
{
    int node = node_base + ((blockIdx.x * blockDim.x + threadIdx.x) >> 5);
    int lane = threadIdx.x & 31;
    if (node >= node_limit) return;

    int beg = __ldg(row_ptr + node);
    int end = __ldg(row_ptr + node + 1);

    const float4* base = reinterpret_cast<const float4*>(y);
    float4 acc = base[(size_t)node * 32 + lane];
    float4 acc2 = make_float4(0.f, 0.f, 0.f, 0.f);

    int j = beg;
    for (; j + 3 < end; j += 4) {
        int c0 = __ldg(col + j);
        int c1 = __ldg(col + j + 1);
        int c2 = __ldg(col + j + 2);
        int c3 = __ldg(col + j + 3);
        float4 v0 = base[(size_t)c0 * 32 + lane];
        float4 v1 = base[(size_t)c1 * 32 + lane];
        float4 v2 = base[(size_t)c2 * 32 + lane];
        float4 v3 = base[(size_t)c3 * 32 + lane];
        acc.x  += v0.x; acc.y  += v0.y; acc.z  += v0.z; acc.w  += v0.w;
        acc2.x += v1.x; acc2.y += v1.y; acc2.z += v1.z; acc2.w += v1.w;
        acc.x  += v2.x; acc.y  += v2.y; acc.z  += v2.z; acc.w  += v2.w;
        acc2.x += v3.x; acc2.y += v3.y; acc2.z += v3.z; acc2.w += v3.w;
    }
    for (; j < end; j++) {
        int c0 = __ldg(col + j);
        float4 v0 = base[(size_t)c0 * 32 + lane];
        acc.x += v0.x; acc.y += v0.y; acc.z += v0.z; acc.w += v0.w;
    }
    acc.x += acc2.x; acc.y += acc2.y; acc.z += acc2.z; acc.w += acc2.w;

    float4 b = reinterpret_cast<const float4*>(bias)[lane];
    float4 o;
    o.x = fmaxf(acc.x + b.x, 0.f);
    o.y = fmaxf(acc.y + b.y, 0.f);
    o.z = fmaxf(acc.z + b.z, 0.f);
    o.w = fmaxf(acc.w + b.w, 0.f);
    reinterpret_cast<float4*>(out)[(size_t)node * 32 + lane] = o;
}

__global__ void __launch_bounds__(256) aggregate64_kernel(
    const float* __restrict__ y, const int* __restrict__ row_ptr,
    const int* __restrict__ col, const float* __restrict__ bias,
    float* __restrict__ out, int node_base, int node_limit)
{
    int node = node_base + ((blockIdx.x * blockDim.x + threadIdx.x) >> 5);
    int lane = threadIdx.x & 31;
    if (node >= node_limit) return;

    int beg = __ldg(row_ptr + node);
    int end = __ldg(row_ptr + node + 1);

    const float2* base = reinterpret_cast<const float2*>(y);
    float2 acc = base[(size_t)node * 32 + lane];
    float2 acc2 = make_float2(0.f, 0.f);

    int j = beg;
    for (; j + 3 < end; j += 4) {
        int c0 = __ldg(col + j);
        int c1 = __ldg(col + j + 1);
        int c2 = __ldg(col + j + 2);
        int c3 = __ldg(col + j + 3);
        float2 v0 = base[(size_t)c0 * 32 + lane];
        float2 v1 = base[(size_t)c1 * 32 + lane];
        float2 v2 = base[(size_t)c2 * 32 + lane];
        float2 v3 = base[(size_t)c3 * 32 + lane];
        acc.x  += v0.x; acc.y  += v0.y;
        acc2.x += v1.x; acc2.y += v1.y;
        acc.x  += v2.x; acc.y  += v2.y;
        acc2.x += v3.x; acc2.y += v3.y;
    }
    for (; j < end; j++) {
        int c0 = __ldg(col + j);
        float2 v0 = base[(size_t)c0 * 32 + lane];
        acc.x += v0.x; acc.y += v0.y;
    }
    acc.x += acc2.x; acc.y += acc2.y;

    float2 b = reinterpret_cast<const float2*>(bias)[lane];
    float2 o;
    o.x = fmaxf(acc.x + b.x, 0.f);
    o.y = fmaxf(acc.y + b.y, 0.f);
    reinterpret_cast<float2*>(out)[(size_t)node * 32 + lane] = o;
}

// ---------------------------------------------------------------------------
// Launch: staggered half pipeline.
//   s0: gemm1 ....[wCSR] agg1A gemm2A ..[wG2B] agg2A gemm3A ..[wG3B] agg3A [wFin]
//   s1: CSR ......[wA1]  agg1B gemm2B .[wA2]  agg2B gemm3B .[wG3A]  agg3B
// Buffers: gemm1→y; agg1:y→h; gemm2:h→z; agg2:z→y; gemm3:y→h; agg3:h→out.
// ---------------------------------------------------------------------------
extern "C" void kernel_launch(void* const* d_in, const int* in_sizes, int n_in,
                              void* d_out, int out_size)
{
    const float* in_feat = (const float*)d_in[0];
    const float* W1 = (const float*)d_in[1];
    const float* b1 = (const float*)d_in[2];
    const float* W2 = (const float*)d_in[3];
    const float* b2 = (const float*)d_in[4];
    const float* W3 = (const float*)d_in[5];
    const float* b3 = (const float*)d_in[6];
    const int*   src = (const int*)d_in[7];
    const int*   dst = (const int*)d_in[8];
    float* out = (float*)d_out;

    float *y, *h, *z;
    int *row_ptr, *cursor, *cnt, *col, *partials;
    cudaGetSymbolAddress((void**)&y, g_y);
    cudaGetSymbolAddress((void**)&h, g_h);
    cudaGetSymbolAddress((void**)&z, g_z);
    cudaGetSymbolAddress((void**)&row_ptr, g_row_ptr);
    cudaGetSymbolAddress((void**)&cursor, g_cursor);
    cudaGetSymbolAddress((void**)&cnt, g_cnt);
    cudaGetSymbolAddress((void**)&col, g_col);
    cudaGetSymbolAddress((void**)&partials, g_partials);

    const int smem128 = (64 * (64 + 4) + 64 * (128 + 4)) * (int)sizeof(float);
    const int smem64  = (64 * (64 + 4) + 64 * (64 + 4))  * (int)sizeof(float);
    cudaFuncSetAttribute(gemm_kernel<128>,
                         cudaFuncAttributeMaxDynamicSharedMemorySize, smem128);
    cudaFuncSetAttribute(gemm_kernel<64>,
                         cudaFuncAttributeMaxDynamicSharedMemorySize, smem64);

    cudaStream_t s0 = 0;
    cudaStream_t s1 = g_ctx.s1;

    const int edge8_blocks = (N_EDGES / 8 + 255) / 256;
    const int gemm_full    = (N_NODES + 63) / 64;
    const int gemm_A       = HALF / 64;                        // 391
    const int gemm_B       = (N_NODES - HALF + 63) / 64;       // 391
    const int agg_A        = (HALF * 32 + 255) / 256;
    const int agg_B        = ((N_NODES - HALF) * 32 + 255) / 256;

    // Fork
    cudaEventRecord(g_ctx.evFork, s0);
    cudaStreamWaitEvent(s1, g_ctx.evFork, 0);

    // s0: gemm1 full ∥ s1: CSR
    gemm_kernel<128><<<gemm_full, 128, smem128, s0>>>(in_feat, W1, y, 0, N_NODES);

    cudaMemsetAsync(cnt, 0, N_NODES * sizeof(int), s1);
    hist_kernel<<<edge8_blocks, 256, 0, s1>>>(dst, cnt);
    scan_block_kernel<<<SCAN_NBLK, SCAN_B, 0, s1>>>(cnt, row_ptr, partials);
    scan_add_kernel<<<SCAN_NBLK, SCAN_B, 0, s1>>>(row_ptr, cursor, partials);
    fill_kernel<<<edge8_blocks, 256, 0, s1>>>(src, dst, cursor, col);
    cudaEventRecord(g_ctx.evCSR, s1);

    // ---- Boundary 1: h = relu(y + Ay + b1); z = h @ W2 ----
    cudaStreamWaitEvent(s0, g_ctx.evCSR, 0);
    aggregate128_kernel<<<agg_A, 256, 0, s0>>>(y, row_ptr, col, b1, h, 0, HALF);
    cudaEventRecord(g_ctx.evA1, s0);
    gemm_kernel<128><<<gemm_A, 128, smem128, s0>>>(h, W2, z, 0, HALF);

    cudaStreamWaitEvent(s1, g_ctx.evA1, 0);   // transitively after gemm1 + CSR
    aggregate128_kernel<<<agg_B, 256, 0, s1>>>(y, row_ptr, col, b1, h, HALF, N_NODES);
    gemm_kernel<128><<<gemm_B, 128, smem128, s1>>>(h, W2, z, HALF, N_NODES);
    cudaEventRecord(g_ctx.evG2B, s1);

    // ---- Boundary 2: y = relu(z + Az + b2); h = y @ W3 (64-d) ----
    cudaStreamWaitEvent(s0, g_ctx.evG2B, 0);
    aggregate128_kernel<<<agg_A, 256, 0, s0>>>(z, row_ptr, col, b2, y, 0, HALF);
    cudaEventRecord(g_ctx.evA2, s0);
    gemm_kernel<64><<<gemm_A, 128, smem64, s0>>>(y, W3, h, 0, HALF);
    cudaEventRecord(g_ctx.evG3A, s0);

    cudaStreamWaitEvent(s1, g_ctx.evA2, 0);
    aggregate128_kernel<<<agg_B, 256, 0, s1>>>(z, row_ptr, col, b2, y, HALF, N_NODES);
    gemm_kernel<64><<<gemm_B, 128, smem64, s1>>>(y, W3, h, HALF, N_NODES);
    cudaEventRecord(g_ctx.evG3B, s1);

    // ---- Final: out = relu(h + Ah + b3), halves concurrent ----
    cudaStreamWaitEvent(s0, g_ctx.evG3B, 0);
    aggregate64_kernel<<<agg_A, 256, 0, s0>>>(h, row_ptr, col, b3, out, 0, HALF);

    cudaStreamWaitEvent(s1, g_ctx.evG3A, 0);
    aggregate64_kernel<<<agg_B, 256, 0, s1>>>(h, row_ptr, col, b3, out, HALF, N_NODES);
    cudaEventRecord(g_ctx.evFinal, s1);

    cudaStreamWaitEvent(s0, g_ctx.evFinal, 0);
}